// round 7
// baseline (speedup 1.0000x reference)
#include <cuda_runtime.h>
#include <cstdint>
#include <math.h>

#define N_TOK 4096
#define DD 1024
#define EE 8
#define HH 2048
#define CAP 4096
#define HROWS (2 * N_TOK + 128)

#define TM 128
#define TN 128
#define KCB 128          // K bytes (int8 elems) per smem chunk
#define SROW 144         // smem row stride (128 data + 16 pad)
#define AHO 0
#define ALO 18432
#define BHO 36864
#define BLO 55296
#define SAO 73728
#define SBO 74240
#define STAGEB 74752     // 73 KB per stage
#define SMEM_BYTES (2 * STAGEB)

#define XCH (DD / 128)   // 8  k-chunks for GEMM1
#define HCH (HH / 128)   // 16 k-chunks for GEMM2

// ---------------- scratch ----------------------------------------------------
__device__ int   g_cnt[EE];
__device__ int   g_tok[EE * CAP];
__device__ float g_gate[EE * CAP];
__device__ __align__(256) char  g_x_h[(size_t)N_TOK * DD];
__device__ __align__(256) char  g_x_l[(size_t)N_TOK * DD];
__device__ __align__(256) float g_xs[(size_t)N_TOK * XCH];
__device__ __align__(256) char  g_w1_h[(size_t)EE * HH * DD];   // [e][n=H][k=D]
__device__ __align__(256) char  g_w1_l[(size_t)EE * HH * DD];
__device__ __align__(256) float g_w1s[(size_t)EE * HH * XCH];
__device__ __align__(256) char  g_w2_h[(size_t)EE * DD * HH];   // [e][n=D][k=H]
__device__ __align__(256) char  g_w2_l[(size_t)EE * DD * HH];
__device__ __align__(256) float g_w2s[(size_t)EE * DD * HCH];
__device__ __align__(256) char  g_h_h[(size_t)HROWS * HH];
__device__ __align__(256) char  g_h_l[(size_t)HROWS * HH];
__device__ __align__(256) float g_hs[(size_t)HROWS * HCH];

// ---------------- PTX helpers -------------------------------------------------
__device__ __forceinline__ uint32_t smem_u32(const void* p) {
    uint32_t a;
    asm("{ .reg .u64 t; cvta.to.shared.u64 t, %1; cvt.u32.u64 %0, t; }"
        : "=r"(a) : "l"(p));
    return a;
}
__device__ __forceinline__ void cp16(uint32_t dst, const void* src, int sz) {
    asm volatile("cp.async.cg.shared.global [%0], [%1], 16, %2;"
                 :: "r"(dst), "l"(src), "r"(sz));
}
__device__ __forceinline__ void cp4(uint32_t dst, const void* src, int sz) {
    asm volatile("cp.async.ca.shared.global [%0], [%1], 4, %2;"
                 :: "r"(dst), "l"(src), "r"(sz));
}
#define CP_COMMIT() asm volatile("cp.async.commit_group;" ::: "memory")
#define CP_WAIT1()  asm volatile("cp.async.wait_group 1;" ::: "memory")
#define CP_WAIT0()  asm volatile("cp.async.wait_group 0;" ::: "memory")

#define LDSM4(R, a) \
    asm volatile("ldmatrix.sync.aligned.m8n8.x4.shared.b16 {%0,%1,%2,%3}, [%4];" \
                 : "=r"((R)[0]), "=r"((R)[1]), "=r"((R)[2]), "=r"((R)[3]) : "r"(a))

#define IMMA(C, A, B0, B1) \
    asm volatile("mma.sync.aligned.m16n8k32.row.col.s32.s8.s8.s32 " \
                 "{%0,%1,%2,%3}, {%4,%5,%6,%7}, {%8,%9}, {%0,%1,%2,%3};" \
                 : "+r"((C)[0]), "+r"((C)[1]), "+r"((C)[2]), "+r"((C)[3]) \
                 : "r"((A)[0]), "r"((A)[1]), "r"((A)[2]), "r"((A)[3]), \
                   "r"(B0), "r"(B1))

// quantize v (given f = 16256/S) -> H, L int8
__device__ __forceinline__ void quant(float v, float f, int& H, int& L) {
    float qf = rintf(v * f);
    float hf = rintf(qf * 0.0078125f);           // /128
    hf = fminf(fmaxf(hf, -127.f), 127.f);
    H = (int)hf;
    L = (int)(qf - 128.f * hf);
}

// ---------------- pre: zero out + counters ------------------------------------
__global__ void k_pre(float* __restrict__ out, int n4) {
    int i = blockIdx.x * blockDim.x + threadIdx.x;
    if (i < n4) ((float4*)out)[i] = make_float4(0.f, 0.f, 0.f, 0.f);
    if (blockIdx.x == 0 && threadIdx.x < EE) g_cnt[threadIdx.x] = 0;
}

// ---------------- conv_w: transpose + int8 quantize both weights --------------
// z<EE: W1 (K=DD,N=HH); z>=EE: W2 (K=HH,N=DD).  Block covers 32 n x 128 k.
__global__ void k_conv_w(const float* __restrict__ W1f,
                         const float* __restrict__ W2f) {
    __shared__ float t[32][129];
    bool isW1 = blockIdx.z < EE;
    int e = isW1 ? blockIdx.z : blockIdx.z - EE;
    int K = isW1 ? DD : HH;
    int N = isW1 ? HH : DD;
    int n0 = blockIdx.x * 32;
    int k0 = blockIdx.y * 128;
    if (n0 >= N || k0 >= K) return;
    const float* We = (isW1 ? W1f : W2f) + (size_t)e * K * N;
    int tx = threadIdx.x, ty = threadIdx.y;
#pragma unroll
    for (int j = 0; j < 16; j++)
        t[tx][j * 8 + ty] = We[(size_t)(k0 + j * 8 + ty) * N + n0 + tx];
    __syncthreads();

    int tid = ty * 32 + tx;
    int r = tid >> 3;          // n row 0..31
    int s = tid & 7;           // k sixteenth 0..7
    float mx = 0.f;
#pragma unroll
    for (int i = 0; i < 16; i++) mx = fmaxf(mx, fabsf(t[r][s * 16 + i]));
#pragma unroll
    for (int o = 1; o < 8; o <<= 1)
        mx = fmaxf(mx, __shfl_xor_sync(0xffffffffu, mx, o));
    float f = mx > 0.f ? 16256.f / mx : 0.f;

    uint32_t wh[4] = {0, 0, 0, 0}, wl[4] = {0, 0, 0, 0};
#pragma unroll
    for (int i = 0; i < 16; i++) {
        int H, L;
        quant(t[r][s * 16 + i], f, H, L);
        wh[i >> 2] |= (uint32_t)(H & 0xFF) << (8 * (i & 3));
        wl[i >> 2] |= (uint32_t)(L & 0xFF) << (8 * (i & 3));
    }
    char* dh = isW1 ? g_w1_h : g_w2_h;
    char* dl = isW1 ? g_w1_l : g_w2_l;
    size_t o = ((size_t)e * N + n0 + r) * K + k0 + s * 16;
    *(uint4*)(dh + o) = *(uint4*)wh;
    *(uint4*)(dl + o) = *(uint4*)wl;
    if (s == 0) {
        float* ds = isW1 ? g_w1s : g_w2s;
        int nch = K / 128;
        ds[((size_t)e * N + n0 + r) * nch + blockIdx.y] = mx * (1.f / 16256.f);
    }
}

// ---------------- router: logits + top2 + x int8 quantization -----------------
__global__ void k_router(const float* __restrict__ x,
                         const float* __restrict__ Wr,
                         const float* __restrict__ br) {
    int tok  = (blockIdx.x * blockDim.x + threadIdx.x) >> 5;
    int lane = threadIdx.x & 31;
    if (tok >= N_TOK) return;
    const float* xr = x + (size_t)tok * DD;
    float acc[EE];
#pragma unroll
    for (int e = 0; e < EE; e++) acc[e] = 0.f;

#pragma unroll
    for (int c = 0; c < XCH; c++) {
        float v[4];
        float mx = 0.f;
#pragma unroll
        for (int j = 0; j < 4; j++) {
            int d = c * 128 + lane + 32 * j;
            v[j] = xr[d];
            mx = fmaxf(mx, fabsf(v[j]));
            const float* w = Wr + d * EE;
#pragma unroll
            for (int e = 0; e < EE; e++) acc[e] += v[j] * w[e];
        }
#pragma unroll
        for (int o = 16; o > 0; o >>= 1)
            mx = fmaxf(mx, __shfl_xor_sync(0xffffffffu, mx, o));
        float f = mx > 0.f ? 16256.f / mx : 0.f;
#pragma unroll
        for (int j = 0; j < 4; j++) {
            int H, L;
            quant(v[j], f, H, L);
            int d = c * 128 + lane + 32 * j;
            g_x_h[(size_t)tok * DD + d] = (char)H;
            g_x_l[(size_t)tok * DD + d] = (char)L;
        }
        if (lane == 0) g_xs[tok * XCH + c] = mx * (1.f / 16256.f);
    }

#pragma unroll
    for (int e = 0; e < EE; e++) {
#pragma unroll
        for (int o = 16; o > 0; o >>= 1)
            acc[e] += __shfl_down_sync(0xffffffffu, acc[e], o);
    }
    if (lane == 0) {
        float lg[EE];
#pragma unroll
        for (int e = 0; e < EE; e++) lg[e] = acc[e] + br[e];
        int i1 = 0;
#pragma unroll
        for (int e = 1; e < EE; e++) if (lg[e] > lg[i1]) i1 = e;
        int i2 = (i1 == 0) ? 1 : 0;
#pragma unroll
        for (int e = 0; e < EE; e++)
            if (e != i1 && lg[e] > lg[i2]) i2 = e;
        float e2 = expf(lg[i2] - lg[i1]);
        float s  = 1.0f + e2;
        int s1 = atomicAdd(&g_cnt[i1], 1);
        g_tok[i1 * CAP + s1]  = tok;
        g_gate[i1 * CAP + s1] = 1.0f / s;
        int s2 = atomicAdd(&g_cnt[i2], 1);
        g_tok[i2 * CAP + s2]  = tok;
        g_gate[i2 * CAP + s2] = e2 / s;
    }
}

// ---------------- IMMA chunk compute (shared by mm1/mm2) ----------------------
__device__ __forceinline__ void imma_chunk(uint32_t st, const char* smem_st,
                                           int mw, int nw, int lane,
                                           float c[2][8][4]) {
    const float* sAf = (const float*)(smem_st + SAO);
    const float* sBf = (const float*)(smem_st + SBO);
    float sa16[2][2], sa128[2][2], sb[8][2];
#pragma unroll
    for (int mf = 0; mf < 2; mf++)
#pragma unroll
        for (int rr = 0; rr < 2; rr++) {
            float s = sAf[mw * 32 + mf * 16 + (lane >> 2) + rr * 8];
            sa16[mf][rr]  = s * 16384.f;
            sa128[mf][rr] = s * 128.f;
        }
#pragma unroll
    for (int nf = 0; nf < 8; nf++)
#pragma unroll
        for (int cc = 0; cc < 2; cc++)
            sb[nf][cc] = sBf[nw * 64 + nf * 8 + 2 * (lane & 3) + cc];

    uint32_t arow = (lane & 7) + 8 * ((lane >> 3) & 1);
    uint32_t acol = 16 * (lane >> 4);
    int acc[2][8][4];

    // ---- pass 1: H x H ----
#pragma unroll
    for (int mf = 0; mf < 2; mf++)
#pragma unroll
        for (int nf = 0; nf < 8; nf++)
#pragma unroll
            for (int q = 0; q < 4; q++) acc[mf][nf][q] = 0;
#pragma unroll
    for (int ks = 0; ks < 4; ks++) {
        uint32_t kb = ks * 32 + acol;
        uint32_t aH[2][4], bH[4][4];
#pragma unroll
        for (int mf = 0; mf < 2; mf++)
            LDSM4(aH[mf], st + AHO + (mw * 32 + mf * 16 + arow) * SROW + kb);
#pragma unroll
        for (int p = 0; p < 4; p++)
            LDSM4(bH[p], st + BHO + (nw * 64 + p * 16 + arow) * SROW + kb);
#pragma unroll
        for (int mf = 0; mf < 2; mf++)
#pragma unroll
            for (int p = 0; p < 4; p++) {
                IMMA(acc[mf][2 * p],     aH[mf], bH[p][0], bH[p][2]);
                IMMA(acc[mf][2 * p + 1], aH[mf], bH[p][1], bH[p][3]);
            }
    }
#pragma unroll
    for (int mf = 0; mf < 2; mf++)
#pragma unroll
        for (int nf = 0; nf < 8; nf++)
#pragma unroll
            for (int q = 0; q < 4; q++)
                c[mf][nf][q] += sa16[mf][q >> 1] * sb[nf][q & 1]
                                * (float)acc[mf][nf][q];

    // ---- pass 2: H x L + L x H ----
#pragma unroll
    for (int mf = 0; mf < 2; mf++)
#pragma unroll
        for (int nf = 0; nf < 8; nf++)
#pragma unroll
            for (int q = 0; q < 4; q++) acc[mf][nf][q] = 0;
#pragma unroll
    for (int ks = 0; ks < 4; ks++) {
        uint32_t kb = ks * 32 + acol;
        uint32_t aH[2][4], aL[2][4], bH[4][4], bL[4][4];
#pragma unroll
        for (int mf = 0; mf < 2; mf++) {
            LDSM4(aH[mf], st + AHO + (mw * 32 + mf * 16 + arow) * SROW + kb);
            LDSM4(aL[mf], st + ALO + (mw * 32 + mf * 16 + arow) * SROW + kb);
        }
#pragma unroll
        for (int p = 0; p < 4; p++) {
            LDSM4(bH[p], st + BHO + (nw * 64 + p * 16 + arow) * SROW + kb);
            LDSM4(bL[p], st + BLO + (nw * 64 + p * 16 + arow) * SROW + kb);
        }
#pragma unroll
        for (int mf = 0; mf < 2; mf++)
#pragma unroll
            for (int p = 0; p < 4; p++) {
                IMMA(acc[mf][2 * p],     aH[mf], bL[p][0], bL[p][2]);
                IMMA(acc[mf][2 * p],     aL[mf], bH[p][0], bH[p][2]);
                IMMA(acc[mf][2 * p + 1], aH[mf], bL[p][1], bL[p][3]);
                IMMA(acc[mf][2 * p + 1], aL[mf], bH[p][1], bH[p][3]);
            }
    }
#pragma unroll
    for (int mf = 0; mf < 2; mf++)
#pragma unroll
        for (int nf = 0; nf < 8; nf++)
#pragma unroll
            for (int q = 0; q < 4; q++)
                c[mf][nf][q] += sa128[mf][q >> 1] * sb[nf][q & 1]
                                * (float)acc[mf][nf][q];
}

// issue one chunk's async loads
__device__ __forceinline__ void load_i8(
    uint32_t st, const char* aH, const char* aL, const char* bH, const char* bL,
    const float* saSrc, const float* sbSrc, int szA, int szS, int tid, int kbyte) {
    int row  = tid >> 1;
    int half = (tid & 1) * 4;
#pragma unroll
    for (int j = 0; j < 4; j++) {
        uint32_t so = (uint32_t)row * SROW + (half + j) * 16;
        int go = kbyte + (half + j) * 16;
        cp16(st + AHO + so, aH + go, szA);
        cp16(st + ALO + so, aL + go, szA);
        cp16(st + BHO + so, bH + go, 16);
        cp16(st + BLO + so, bL + go, 16);
    }
    if (tid < 128) cp4(st + SAO + tid * 4, saSrc, szS);
    else           cp4(st + SBO + (tid - 128) * 4, sbSrc, 4);
}

// ---------------- GEMM1: h = relu(Xg @ W1^T + b1) -> int8 (H,L) + scales ------
__global__ void __launch_bounds__(256) k_mm1(const float* __restrict__ b1) {
    extern __shared__ char smem[];
    int e   = blockIdx.z;
    int cnt = g_cnt[e];
    int m0  = blockIdx.y * TM;
    if (m0 >= cnt) return;
    int n0  = blockIdx.x * TN;
    int off = 0;
    for (int i = 0; i < e; i++) off += g_cnt[i];
    int tid = threadIdx.x, wid = tid >> 5, lane = tid & 31;
    int mw = wid & 3, nw = wid >> 2;
    uint32_t sbase = smem_u32(smem);

    int drow = tid >> 1;
    bool rokA = (m0 + drow) < cnt;
    int tokA = rokA ? g_tok[e * CAP + m0 + drow] : 0;
    const char* aH = g_x_h + (size_t)tokA * DD;
    const char* aL = g_x_l + (size_t)tokA * DD;
    const char* bH = g_w1_h + ((size_t)e * HH + n0 + drow) * DD;
    const char* bL = g_w1_l + ((size_t)e * HH + n0 + drow) * DD;
    const float* saSrc = g_xs;
    const float* sbSrc = g_w1s;
    int szS = 0;
    if (tid < 128) {
        bool rokS = (m0 + tid) < cnt;
        int tokS = rokS ? g_tok[e * CAP + m0 + tid] : 0;
        saSrc = g_xs + (size_t)tokS * XCH;
        szS = rokS ? 4 : 0;
    } else {
        sbSrc = g_w1s + ((size_t)e * HH + n0 + tid - 128) * XCH;
    }
    int szA = rokA ? 16 : 0;

    float c[2][8][4];
#pragma unroll
    for (int i = 0; i < 2; i++)
#pragma unroll
        for (int j = 0; j < 8; j++)
#pragma unroll
            for (int q = 0; q < 4; q++) c[i][j][q] = 0.f;

    load_i8(sbase, aH, aL, bH, bL, saSrc, sbSrc, szA, szS, tid, 0);
    CP_COMMIT();
    for (int ch = 0; ch < XCH; ch++) {
        if (ch + 1 < XCH) {
            load_i8(sbase + ((ch + 1) & 1) * STAGEB, aH, aL, bH, bL,
                    saSrc + ch + 1, sbSrc + ch + 1, szA, szS, tid,
                    (ch + 1) * KCB);
            CP_COMMIT();
            CP_WAIT1();
        } else {
            CP_WAIT0();
        }
        __syncthreads();
        uint32_t st = sbase + (ch & 1) * STAGEB;
        imma_chunk(st, smem + (ch & 1) * STAGEB, mw, nw, lane, c);
        __syncthreads();
    }

    // ---- epilogue: bias + relu, row-max over 128 cols, int8 quant store ------
    const float* b1e = b1 + (size_t)e * HH + n0;
    float colb[8][2];
#pragma unroll
    for (int nf = 0; nf < 8; nf++)
#pragma unroll
        for (int cc = 0; cc < 2; cc++)
            colb[nf][cc] = b1e[nw * 64 + nf * 8 + 2 * (lane & 3) + cc];
#pragma unroll
    for (int mf = 0; mf < 2; mf++)
#pragma unroll
        for (int nf = 0; nf < 8; nf++)
#pragma unroll
            for (int q = 0; q < 4; q++)
                c[mf][nf][q] = fmaxf(c[mf][nf][q] + colb[nf][q & 1], 0.f);

    float* rmax = (float*)smem;   // [128][2]
#pragma unroll
    for (int mf = 0; mf < 2; mf++)
#pragma unroll
        for (int rr = 0; rr < 2; rr++) {
            float m = 0.f;
#pragma unroll
            for (int nf = 0; nf < 8; nf++) {
                m = fmaxf(m, c[mf][nf][rr * 2]);
                m = fmaxf(m, c[mf][nf][rr * 2 + 1]);
            }
            m = fmaxf(m, __shfl_xor_sync(0xffffffffu, m, 1));
            m = fmaxf(m, __shfl_xor_sync(0xffffffffu, m, 2));
            if ((lane & 3) == 0)
                rmax[(mw * 32 + mf * 16 + (lane >> 2) + rr * 8) * 2 + nw] = m;
        }
    __syncthreads();
#pragma unroll
    for (int mf = 0; mf < 2; mf++)
#pragma unroll
        for (int rr = 0; rr < 2; rr++) {
            int rowi = mw * 32 + mf * 16 + (lane >> 2) + rr * 8;
            int m = m0 + rowi;
            if (m >= cnt) continue;
            float S = fmaxf(rmax[rowi * 2], rmax[rowi * 2 + 1]);
            float f = S > 0.f ? 16256.f / S : 0.f;
            size_t hrow = (size_t)(off + m);
#pragma unroll
            for (int nf = 0; nf < 8; nf++) {
                int H0, L0, H1, L1;
                quant(c[mf][nf][rr * 2],     f, H0, L0);
                quant(c[mf][nf][rr * 2 + 1], f, H1, L1);
                int col = n0 + nw * 64 + nf * 8 + 2 * (lane & 3);
                uchar2 vh, vl;
                vh.x = (unsigned char)(H0 & 0xFF); vh.y = (unsigned char)(H1 & 0xFF);
                vl.x = (unsigned char)(L0 & 0xFF); vl.y = (unsigned char)(L1 & 0xFF);
                *(uchar2*)(g_h_h + hrow * HH + col) = vh;
                *(uchar2*)(g_h_l + hrow * HH + col) = vl;
            }
            if (nw == 0 && (lane & 3) == 0)
                g_hs[hrow * HCH + blockIdx.x] = S * (1.f / 16256.f);
        }
}

// ---------------- GEMM2: out[tok] += gate * (h @ W2^T + b2) -------------------
__global__ void __launch_bounds__(256) k_mm2(const float* __restrict__ b2,
                                             float* __restrict__ out) {
    extern __shared__ char smem[];
    int e   = blockIdx.z;
    int cnt = g_cnt[e];
    int m0  = blockIdx.y * TM;
    if (m0 >= cnt) return;
    int n0  = blockIdx.x * TN;
    int off = 0;
    for (int i = 0; i < e; i++) off += g_cnt[i];
    int tid = threadIdx.x, wid = tid >> 5, lane = tid & 31;
    int mw = wid & 3, nw = wid >> 2;
    uint32_t sbase = smem_u32(smem);

    int drow = tid >> 1;
    bool rokA = (m0 + drow) < cnt;
    const char* aH = g_h_h + (size_t)(off + m0 + drow) * HH;
    const char* aL = g_h_l + (size_t)(off + m0 + drow) * HH;
    const char* bH = g_w2_h + ((size_t)e * DD + n0 + drow) * HH;
    const char* bL = g_w2_l + ((size_t)e * DD + n0 + drow) * HH;
    const float* saSrc = g_hs;
    const float* sbSrc = g_w2s;
    int szS = 0;
    if (tid < 128) {
        bool rokS = (m0 + tid) < cnt;
        saSrc = g_hs + (size_t)(off + m0 + (rokS ? tid : 0)) * HCH;
        szS = rokS ? 4 : 0;
    } else {
        sbSrc = g_w2s + ((size_t)e * DD + n0 + tid - 128) * HCH;
    }
    int szA = rokA ? 16 : 0;

    float c[2][8][4];
#pragma unroll
    for (int i = 0; i < 2; i++)
#pragma unroll
        for (int j = 0; j < 8; j++)
#pragma unroll
            for (int q = 0; q < 4; q++) c[i][j][q] = 0.f;

    load_i8(sbase, aH, aL, bH, bL, saSrc, sbSrc, szA, szS, tid, 0);
    CP_COMMIT();
    for (int ch = 0; ch < HCH; ch++) {
        if (ch + 1 < HCH) {
            load_i8(sbase + ((ch + 1) & 1) * STAGEB, aH, aL, bH, bL,
                    saSrc + ch + 1, sbSrc + ch + 1, szA, szS, tid,
                    (ch + 1) * KCB);
            CP_COMMIT();
            CP_WAIT1();
        } else {
            CP_WAIT0();
        }
        __syncthreads();
        uint32_t st = sbase + (ch & 1) * STAGEB;
        imma_chunk(st, smem + (ch & 1) * STAGEB, mw, nw, lane, c);
        __syncthreads();
    }

    const float* b2e = b2 + (size_t)e * DD + n0;
#pragma unroll
    for (int mf = 0; mf < 2; mf++)
#pragma unroll
        for (int rr = 0; rr < 2; rr++) {
            int rowi = mw * 32 + mf * 16 + (lane >> 2) + rr * 8;
            int m = m0 + rowi;
            if (m >= cnt) continue;
            int   tok  = g_tok[e * CAP + m];
            float gate = g_gate[e * CAP + m];
            float* orow = out + (size_t)tok * DD + n0;
#pragma unroll
            for (int nf = 0; nf < 8; nf++) {
                int col = nw * 64 + nf * 8 + 2 * (lane & 3);
                atomicAdd(orow + col,
                          gate * (c[mf][nf][rr * 2] + b2e[col]));
                atomicAdd(orow + col + 1,
                          gate * (c[mf][nf][rr * 2 + 1] + b2e[col + 1]));
            }
        }
}

// ---------------- launch ------------------------------------------------------
extern "C" void kernel_launch(void* const* d_in, const int* in_sizes, int n_in,
                              void* d_out, int out_size) {
    const float* x  = (const float*)d_in[0];
    const float* Wr = (const float*)d_in[1];
    const float* br = (const float*)d_in[2];
    const float* W1 = (const float*)d_in[3];
    const float* b1 = (const float*)d_in[4];
    const float* W2 = (const float*)d_in[5];
    const float* b2 = (const float*)d_in[6];
    float* out = (float*)d_out;

    cudaFuncSetAttribute(k_mm1, cudaFuncAttributeMaxDynamicSharedMemorySize, SMEM_BYTES);
    cudaFuncSetAttribute(k_mm2, cudaFuncAttributeMaxDynamicSharedMemorySize, SMEM_BYTES);

    int n4 = out_size / 4;
    k_pre<<<(n4 + 255) / 256, 256>>>(out, n4);                          // 0
    k_conv_w<<<dim3(64, 16, 2 * EE), dim3(32, 8)>>>(W1, W2);            // 1
    k_router<<<(N_TOK * 32 + 255) / 256, 256>>>(x, Wr, br);             // 2
    k_mm1<<<dim3(HH / TN, N_TOK / TM, EE), 256, SMEM_BYTES>>>(b1);      // 3 (profiled)
    k_mm2<<<dim3(DD / TN, N_TOK / TM, EE), 256, SMEM_BYTES>>>(b2, out); // 4
}

// round 8
// speedup vs baseline: 1.6459x; 1.6459x over previous
#include <cuda_runtime.h>
#include <cstdint>
#include <math.h>

#define N_TOK 4096
#define DD 1024
#define EE 8
#define HH 2048
#define CAP 4096
#define HROWS (2 * N_TOK + 128)

#define TM 128
#define TN 128
#define NT 512           // threads per GEMM CTA (16 warps)
#define KCB 128          // K bytes (int8 elems) per smem chunk
#define SROW 144         // smem row stride (128 data + 16 pad)
#define AHO 0
#define ALO 18432
#define BHO 36864
#define BLO 55296
#define SAO 73728
#define SBO 74240
#define STAGEB 74752
#define SMEM_BYTES (2 * STAGEB)

#define XCH (DD / 128)   // 8  k-chunks for GEMM1
#define HCH (HH / 128)   // 16 k-chunks for GEMM2

// ---------------- scratch ----------------------------------------------------
__device__ int   g_cnt[EE];
__device__ int   g_tok[EE * CAP];
__device__ float g_gate[EE * CAP];
__device__ __align__(256) char  g_x_h[(size_t)N_TOK * DD];
__device__ __align__(256) char  g_x_l[(size_t)N_TOK * DD];
__device__ __align__(256) float g_xs[(size_t)N_TOK * XCH];
__device__ __align__(256) char  g_w1_h[(size_t)EE * HH * DD];   // [e][n=H][k=D]
__device__ __align__(256) char  g_w1_l[(size_t)EE * HH * DD];
__device__ __align__(256) float g_w1s[(size_t)EE * HH * XCH];
__device__ __align__(256) char  g_w2_h[(size_t)EE * DD * HH];   // [e][n=D][k=H]
__device__ __align__(256) char  g_w2_l[(size_t)EE * DD * HH];
__device__ __align__(256) float g_w2s[(size_t)EE * DD * HCH];
__device__ __align__(256) char  g_h_h[(size_t)HROWS * HH];
__device__ __align__(256) char  g_h_l[(size_t)HROWS * HH];
__device__ __align__(256) float g_hs[(size_t)HROWS * HCH];

// ---------------- PTX helpers -------------------------------------------------
__device__ __forceinline__ uint32_t smem_u32(const void* p) {
    uint32_t a;
    asm("{ .reg .u64 t; cvta.to.shared.u64 t, %1; cvt.u32.u64 %0, t; }"
        : "=r"(a) : "l"(p));
    return a;
}
__device__ __forceinline__ void cp16(uint32_t dst, const void* src, int sz) {
    asm volatile("cp.async.cg.shared.global [%0], [%1], 16, %2;"
                 :: "r"(dst), "l"(src), "r"(sz));
}
__device__ __forceinline__ void cp4(uint32_t dst, const void* src, int sz) {
    asm volatile("cp.async.ca.shared.global [%0], [%1], 4, %2;"
                 :: "r"(dst), "l"(src), "r"(sz));
}
#define CP_COMMIT() asm volatile("cp.async.commit_group;" ::: "memory")
#define CP_WAIT1()  asm volatile("cp.async.wait_group 1;" ::: "memory")
#define CP_WAIT0()  asm volatile("cp.async.wait_group 0;" ::: "memory")

#define LDSM4(R, a) \
    asm volatile("ldmatrix.sync.aligned.m8n8.x4.shared.b16 {%0,%1,%2,%3}, [%4];" \
                 : "=r"((R)[0]), "=r"((R)[1]), "=r"((R)[2]), "=r"((R)[3]) : "r"(a))

#define IMMA(C, A, B0, B1) \
    asm volatile("mma.sync.aligned.m16n8k32.row.col.s32.s8.s8.s32 " \
                 "{%0,%1,%2,%3}, {%4,%5,%6,%7}, {%8,%9}, {%0,%1,%2,%3};" \
                 : "+r"((C)[0]), "+r"((C)[1]), "+r"((C)[2]), "+r"((C)[3]) \
                 : "r"((A)[0]), "r"((A)[1]), "r"((A)[2]), "r"((A)[3]), \
                   "r"(B0), "r"(B1))

// quantize v (given f = 16256/S) -> H, L int8
__device__ __forceinline__ void quant(float v, float f, int& H, int& L) {
    float qf = rintf(v * f);
    float hf = rintf(qf * 0.0078125f);           // /128
    hf = fminf(fmaxf(hf, -127.f), 127.f);
    H = (int)hf;
    L = (int)(qf - 128.f * hf);
}

// ---------------- pre: zero out + counters ------------------------------------
__global__ void k_pre(float* __restrict__ out, int n4) {
    int i = blockIdx.x * blockDim.x + threadIdx.x;
    if (i < n4) ((float4*)out)[i] = make_float4(0.f, 0.f, 0.f, 0.f);
    if (blockIdx.x == 0 && threadIdx.x < EE) g_cnt[threadIdx.x] = 0;
}

// ---------------- conv_w: transpose + int8 quantize both weights --------------
__global__ void k_conv_w(const float* __restrict__ W1f,
                         const float* __restrict__ W2f) {
    __shared__ float t[32][129];
    bool isW1 = blockIdx.z < EE;
    int e = isW1 ? blockIdx.z : blockIdx.z - EE;
    int K = isW1 ? DD : HH;
    int N = isW1 ? HH : DD;
    int n0 = blockIdx.x * 32;
    int k0 = blockIdx.y * 128;
    if (n0 >= N || k0 >= K) return;
    const float* We = (isW1 ? W1f : W2f) + (size_t)e * K * N;
    int tx = threadIdx.x, ty = threadIdx.y;
#pragma unroll
    for (int j = 0; j < 16; j++)
        t[tx][j * 8 + ty] = We[(size_t)(k0 + j * 8 + ty) * N + n0 + tx];
    __syncthreads();

    int tid = ty * 32 + tx;
    int r = tid >> 3;
    int s = tid & 7;
    float mx = 0.f;
#pragma unroll
    for (int i = 0; i < 16; i++) mx = fmaxf(mx, fabsf(t[r][s * 16 + i]));
#pragma unroll
    for (int o = 1; o < 8; o <<= 1)
        mx = fmaxf(mx, __shfl_xor_sync(0xffffffffu, mx, o));
    float f = mx > 0.f ? 16256.f / mx : 0.f;

    uint32_t wh[4] = {0, 0, 0, 0}, wl[4] = {0, 0, 0, 0};
#pragma unroll
    for (int i = 0; i < 16; i++) {
        int H, L;
        quant(t[r][s * 16 + i], f, H, L);
        wh[i >> 2] |= (uint32_t)(H & 0xFF) << (8 * (i & 3));
        wl[i >> 2] |= (uint32_t)(L & 0xFF) << (8 * (i & 3));
    }
    char* dh = isW1 ? g_w1_h : g_w2_h;
    char* dl = isW1 ? g_w1_l : g_w2_l;
    size_t o = ((size_t)e * N + n0 + r) * K + k0 + s * 16;
    *(uint4*)(dh + o) = *(uint4*)wh;
    *(uint4*)(dl + o) = *(uint4*)wl;
    if (s == 0) {
        float* ds = isW1 ? g_w1s : g_w2s;
        int nch = K / 128;
        ds[((size_t)e * N + n0 + r) * nch + blockIdx.y] = mx * (1.f / 16256.f);
    }
}

// ---------------- router: logits + top2 + x int8 quantization -----------------
__global__ void k_router(const float* __restrict__ x,
                         const float* __restrict__ Wr,
                         const float* __restrict__ br) {
    int tok  = (blockIdx.x * blockDim.x + threadIdx.x) >> 5;
    int lane = threadIdx.x & 31;
    if (tok >= N_TOK) return;
    const float* xr = x + (size_t)tok * DD;
    float acc[EE];
#pragma unroll
    for (int e = 0; e < EE; e++) acc[e] = 0.f;

#pragma unroll
    for (int c = 0; c < XCH; c++) {
        float v[4];
        float mx = 0.f;
#pragma unroll
        for (int j = 0; j < 4; j++) {
            int d = c * 128 + lane + 32 * j;
            v[j] = xr[d];
            mx = fmaxf(mx, fabsf(v[j]));
            const float* w = Wr + d * EE;
#pragma unroll
            for (int e = 0; e < EE; e++) acc[e] += v[j] * w[e];
        }
#pragma unroll
        for (int o = 16; o > 0; o >>= 1)
            mx = fmaxf(mx, __shfl_xor_sync(0xffffffffu, mx, o));
        float f = mx > 0.f ? 16256.f / mx : 0.f;
#pragma unroll
        for (int j = 0; j < 4; j++) {
            int H, L;
            quant(v[j], f, H, L);
            int d = c * 128 + lane + 32 * j;
            g_x_h[(size_t)tok * DD + d] = (char)H;
            g_x_l[(size_t)tok * DD + d] = (char)L;
        }
        if (lane == 0) g_xs[tok * XCH + c] = mx * (1.f / 16256.f);
    }

#pragma unroll
    for (int e = 0; e < EE; e++) {
#pragma unroll
        for (int o = 16; o > 0; o >>= 1)
            acc[e] += __shfl_down_sync(0xffffffffu, acc[e], o);
    }
    if (lane == 0) {
        float lg[EE];
#pragma unroll
        for (int e = 0; e < EE; e++) lg[e] = acc[e] + br[e];
        int i1 = 0;
#pragma unroll
        for (int e = 1; e < EE; e++) if (lg[e] > lg[i1]) i1 = e;
        int i2 = (i1 == 0) ? 1 : 0;
#pragma unroll
        for (int e = 0; e < EE; e++)
            if (e != i1 && lg[e] > lg[i2]) i2 = e;
        float e2 = expf(lg[i2] - lg[i1]);
        float s  = 1.0f + e2;
        int s1 = atomicAdd(&g_cnt[i1], 1);
        g_tok[i1 * CAP + s1]  = tok;
        g_gate[i1 * CAP + s1] = 1.0f / s;
        int s2 = atomicAdd(&g_cnt[i2], 1);
        g_tok[i2 * CAP + s2]  = tok;
        g_gate[i2 * CAP + s2] = e2 / s;
    }
}

// ---------------- IMMA chunk compute: warp tile 32(m) x 32(n) -----------------
__device__ __forceinline__ void imma_chunk(uint32_t st, const char* smem_st,
                                           int mw, int nw, int lane,
                                           float c[2][4][4]) {
    const float* sAf = (const float*)(smem_st + SAO);
    const float* sBf = (const float*)(smem_st + SBO);
    float sa16[2][2], sa128[2][2], sb[4][2];
#pragma unroll
    for (int mf = 0; mf < 2; mf++)
#pragma unroll
        for (int rr = 0; rr < 2; rr++) {
            float s = sAf[mw * 32 + mf * 16 + (lane >> 2) + rr * 8];
            sa16[mf][rr]  = s * 16384.f;
            sa128[mf][rr] = s * 128.f;
        }
#pragma unroll
    for (int nf = 0; nf < 4; nf++)
#pragma unroll
        for (int cc = 0; cc < 2; cc++)
            sb[nf][cc] = sBf[nw * 32 + nf * 8 + 2 * (lane & 3) + cc];

    uint32_t arow = (lane & 7) + 8 * ((lane >> 3) & 1);
    uint32_t acol = 16 * (lane >> 4);
    int acc[2][4][4];

    // ---- pass 1: H x H ----
#pragma unroll
    for (int mf = 0; mf < 2; mf++)
#pragma unroll
        for (int nf = 0; nf < 4; nf++)
#pragma unroll
            for (int q = 0; q < 4; q++) acc[mf][nf][q] = 0;
#pragma unroll
    for (int ks = 0; ks < 4; ks++) {
        uint32_t kb = ks * 32 + acol;
        uint32_t aH[2][4], bH[2][4];
#pragma unroll
        for (int mf = 0; mf < 2; mf++)
            LDSM4(aH[mf], st + AHO + (mw * 32 + mf * 16 + arow) * SROW + kb);
#pragma unroll
        for (int p = 0; p < 2; p++)
            LDSM4(bH[p], st + BHO + (nw * 32 + p * 16 + arow) * SROW + kb);
#pragma unroll
        for (int mf = 0; mf < 2; mf++)
#pragma unroll
            for (int p = 0; p < 2; p++) {
                IMMA(acc[mf][2 * p],     aH[mf], bH[p][0], bH[p][2]);
                IMMA(acc[mf][2 * p + 1], aH[mf], bH[p][1], bH[p][3]);
            }
    }
#pragma unroll
    for (int mf = 0; mf < 2; mf++)
#pragma unroll
        for (int nf = 0; nf < 4; nf++)
#pragma unroll
            for (int q = 0; q < 4; q++)
                c[mf][nf][q] += sa16[mf][q >> 1] * sb[nf][q & 1]
                                * (float)acc[mf][nf][q];

    // ---- pass 2: H x L + L x H ----
#pragma unroll
    for (int mf = 0; mf < 2; mf++)
#pragma unroll
        for (int nf = 0; nf < 4; nf++)
#pragma unroll
            for (int q = 0; q < 4; q++) acc[mf][nf][q] = 0;
#pragma unroll
    for (int ks = 0; ks < 4; ks++) {
        uint32_t kb = ks * 32 + acol;
        uint32_t aH[2][4], aL[2][4], bH[2][4], bL[2][4];
#pragma unroll
        for (int mf = 0; mf < 2; mf++) {
            LDSM4(aH[mf], st + AHO + (mw * 32 + mf * 16 + arow) * SROW + kb);
            LDSM4(aL[mf], st + ALO + (mw * 32 + mf * 16 + arow) * SROW + kb);
        }
#pragma unroll
        for (int p = 0; p < 2; p++) {
            LDSM4(bH[p], st + BHO + (nw * 32 + p * 16 + arow) * SROW + kb);
            LDSM4(bL[p], st + BLO + (nw * 32 + p * 16 + arow) * SROW + kb);
        }
#pragma unroll
        for (int mf = 0; mf < 2; mf++)
#pragma unroll
            for (int p = 0; p < 2; p++) {
                IMMA(acc[mf][2 * p],     aH[mf], bL[p][0], bL[p][2]);
                IMMA(acc[mf][2 * p],     aL[mf], bH[p][0], bH[p][2]);
                IMMA(acc[mf][2 * p + 1], aH[mf], bL[p][1], bL[p][3]);
                IMMA(acc[mf][2 * p + 1], aL[mf], bH[p][1], bH[p][3]);
            }
    }
#pragma unroll
    for (int mf = 0; mf < 2; mf++)
#pragma unroll
        for (int nf = 0; nf < 4; nf++)
#pragma unroll
            for (int q = 0; q < 4; q++)
                c[mf][nf][q] += sa128[mf][q >> 1] * sb[nf][q & 1]
                                * (float)acc[mf][nf][q];
}

// issue one chunk's async loads (512 threads: 8 x cp16 + scale each)
__device__ __forceinline__ void load_i8(
    uint32_t st, const char* aH, const char* aL, const char* bH, const char* bL,
    const float* saSrc, const float* sbSrc, int szA, int szS, int tid, int kbyte) {
    int row = tid >> 2;
    int j0  = (tid & 3) * 2;
#pragma unroll
    for (int j = j0; j < j0 + 2; j++) {
        uint32_t so = (uint32_t)row * SROW + j * 16;
        int go = kbyte + j * 16;
        cp16(st + AHO + so, aH + go, szA);
        cp16(st + ALO + so, aL + go, szA);
        cp16(st + BHO + so, bH + go, 16);
        cp16(st + BLO + so, bL + go, 16);
    }
    if (tid < 128)      cp4(st + SAO + tid * 4, saSrc, szS);
    else if (tid < 256) cp4(st + SBO + (tid - 128) * 4, sbSrc, 4);
}

// ---------------- GEMM1: h = relu(Xg @ W1^T + b1) -> int8 (H,L) + scales ------
__global__ void __launch_bounds__(NT) k_mm1(const float* __restrict__ b1) {
    extern __shared__ char smem[];
    int e   = blockIdx.z;
    int cnt = g_cnt[e];
    int m0  = blockIdx.y * TM;
    if (m0 >= cnt) return;
    int n0  = blockIdx.x * TN;
    int off = 0;
    for (int i = 0; i < e; i++) off += g_cnt[i];
    int tid = threadIdx.x, wid = tid >> 5, lane = tid & 31;
    int mw = wid & 3, nw = wid >> 2;
    uint32_t sbase = smem_u32(smem);

    int drow = tid >> 2;
    bool rokA = (m0 + drow) < cnt;
    int tokA = rokA ? g_tok[e * CAP + m0 + drow] : 0;
    const char* aH = g_x_h + (size_t)tokA * DD;
    const char* aL = g_x_l + (size_t)tokA * DD;
    const char* bH = g_w1_h + ((size_t)e * HH + n0 + drow) * DD;
    const char* bL = g_w1_l + ((size_t)e * HH + n0 + drow) * DD;
    const float* saSrc = g_xs;
    const float* sbSrc = g_w1s;
    int szS = 0;
    if (tid < 128) {
        bool rokS = (m0 + tid) < cnt;
        int tokS = rokS ? g_tok[e * CAP + m0 + tid] : 0;
        saSrc = g_xs + (size_t)tokS * XCH;
        szS = rokS ? 4 : 0;
    } else if (tid < 256) {
        sbSrc = g_w1s + ((size_t)e * HH + n0 + tid - 128) * XCH;
    }
    int szA = rokA ? 16 : 0;

    float c[2][4][4];
#pragma unroll
    for (int i = 0; i < 2; i++)
#pragma unroll
        for (int j = 0; j < 4; j++)
#pragma unroll
            for (int q = 0; q < 4; q++) c[i][j][q] = 0.f;

    load_i8(sbase, aH, aL, bH, bL, saSrc, sbSrc, szA, szS, tid, 0);
    CP_COMMIT();
    for (int ch = 0; ch < XCH; ch++) {
        if (ch + 1 < XCH) {
            load_i8(sbase + ((ch + 1) & 1) * STAGEB, aH, aL, bH, bL,
                    saSrc + ch + 1, sbSrc + ch + 1, szA, szS, tid,
                    (ch + 1) * KCB);
            CP_COMMIT();
            CP_WAIT1();
        } else {
            CP_WAIT0();
        }
        __syncthreads();
        uint32_t st = sbase + (ch & 1) * STAGEB;
        imma_chunk(st, smem + (ch & 1) * STAGEB, mw, nw, lane, c);
        __syncthreads();
    }

    // ---- epilogue: bias + relu, row-max over 128 cols, int8 quant store ------
    const float* b1e = b1 + (size_t)e * HH + n0;
#pragma unroll
    for (int mf = 0; mf < 2; mf++)
#pragma unroll
        for (int nf = 0; nf < 4; nf++)
#pragma unroll
            for (int q = 0; q < 4; q++) {
                float bb = b1e[nw * 32 + nf * 8 + 2 * (lane & 3) + (q & 1)];
                c[mf][nf][q] = fmaxf(c[mf][nf][q] + bb, 0.f);
            }

    float* rmax = (float*)smem;   // [128][4]
#pragma unroll
    for (int mf = 0; mf < 2; mf++)
#pragma unroll
        for (int rr = 0; rr < 2; rr++) {
            float m = 0.f;
#pragma unroll
            for (int nf = 0; nf < 4; nf++) {
                m = fmaxf(m, c[mf][nf][rr * 2]);
                m = fmaxf(m, c[mf][nf][rr * 2 + 1]);
            }
            m = fmaxf(m, __shfl_xor_sync(0xffffffffu, m, 1));
            m = fmaxf(m, __shfl_xor_sync(0xffffffffu, m, 2));
            if ((lane & 3) == 0)
                rmax[(mw * 32 + mf * 16 + (lane >> 2) + rr * 8) * 4 + nw] = m;
        }
    __syncthreads();
#pragma unroll
    for (int mf = 0; mf < 2; mf++)
#pragma unroll
        for (int rr = 0; rr < 2; rr++) {
            int rowi = mw * 32 + mf * 16 + (lane >> 2) + rr * 8;
            int m = m0 + rowi;
            if (m >= cnt) continue;
            float S = fmaxf(fmaxf(rmax[rowi * 4], rmax[rowi * 4 + 1]),
                            fmaxf(rmax[rowi * 4 + 2], rmax[rowi * 4 + 3]));
            float f = S > 0.f ? 16256.f / S : 0.f;
            size_t hrow = (size_t)(off + m);
#pragma unroll
            for (int nf = 0; nf < 4; nf++) {
                int H0, L0, H1, L1;
                quant(c[mf][nf][rr * 2],     f, H0, L0);
                quant(c[mf][nf][rr * 2 + 1], f, H1, L1);
                int col = n0 + nw * 32 + nf * 8 + 2 * (lane & 3);
                uchar2 vh, vl;
                vh.x = (unsigned char)(H0 & 0xFF); vh.y = (unsigned char)(H1 & 0xFF);
                vl.x = (unsigned char)(L0 & 0xFF); vl.y = (unsigned char)(L1 & 0xFF);
                *(uchar2*)(g_h_h + hrow * HH + col) = vh;
                *(uchar2*)(g_h_l + hrow * HH + col) = vl;
            }
            if (nw == 0 && (lane & 3) == 0)
                g_hs[hrow * HCH + blockIdx.x] = S * (1.f / 16256.f);
        }
}

// ---------------- GEMM2: out[tok] += gate * (h @ W2^T + b2) -------------------
__global__ void __launch_bounds__(NT) k_mm2(const float* __restrict__ b2,
                                            float* __restrict__ out) {
    extern __shared__ char smem[];
    int e   = blockIdx.z;
    int cnt = g_cnt[e];
    int m0  = blockIdx.y * TM;
    if (m0 >= cnt) return;
    int n0  = blockIdx.x * TN;
    int off = 0;
    for (int i = 0; i < e; i++) off += g_cnt[i];
    int tid = threadIdx.x, wid = tid >> 5, lane = tid & 31;
    int mw = wid & 3, nw = wid >> 2;
    uint32_t sbase = smem_u32(smem);

    int drow = tid >> 2;
    bool rokA = (m0 + drow) < cnt;
    const char* aH = g_h_h + (size_t)(off + m0 + drow) * HH;
    const char* aL = g_h_l + (size_t)(off + m0 + drow) * HH;
    const char* bH = g_w2_h + ((size_t)e * DD + n0 + drow) * HH;
    const char* bL = g_w2_l + ((size_t)e * DD + n0 + drow) * HH;
    const float* saSrc = g_hs;
    const float* sbSrc = g_w2s;
    int szS = 0;
    if (tid < 128) {
        bool rokS = (m0 + tid) < cnt;
        saSrc = g_hs + (size_t)(off + m0 + (rokS ? tid : 0)) * HCH;
        szS = rokS ? 4 : 0;
    } else if (tid < 256) {
        sbSrc = g_w2s + ((size_t)e * DD + n0 + tid - 128) * HCH;
    }
    int szA = rokA ? 16 : 0;

    float c[2][4][4];
#pragma unroll
    for (int i = 0; i < 2; i++)
#pragma unroll
        for (int j = 0; j < 4; j++)
#pragma unroll
            for (int q = 0; q < 4; q++) c[i][j][q] = 0.f;

    load_i8(sbase, aH, aL, bH, bL, saSrc, sbSrc, szA, szS, tid, 0);
    CP_COMMIT();
    for (int ch = 0; ch < HCH; ch++) {
        if (ch + 1 < HCH) {
            load_i8(sbase + ((ch + 1) & 1) * STAGEB, aH, aL, bH, bL,
                    saSrc + ch + 1, sbSrc + ch + 1, szA, szS, tid,
                    (ch + 1) * KCB);
            CP_COMMIT();
            CP_WAIT1();
        } else {
            CP_WAIT0();
        }
        __syncthreads();
        uint32_t st = sbase + (ch & 1) * STAGEB;
        imma_chunk(st, smem + (ch & 1) * STAGEB, mw, nw, lane, c);
        __syncthreads();
    }

    const float* b2e = b2 + (size_t)e * DD + n0;
#pragma unroll
    for (int mf = 0; mf < 2; mf++)
#pragma unroll
        for (int rr = 0; rr < 2; rr++) {
            int rowi = mw * 32 + mf * 16 + (lane >> 2) + rr * 8;
            int m = m0 + rowi;
            if (m >= cnt) continue;
            int   tok  = g_tok[e * CAP + m];
            float gate = g_gate[e * CAP + m];
            float* orow = out + (size_t)tok * DD + n0;
#pragma unroll
            for (int nf = 0; nf < 4; nf++) {
                int col = nw * 32 + nf * 8 + 2 * (lane & 3);
                atomicAdd(orow + col,
                          gate * (c[mf][nf][rr * 2] + b2e[col]));
                atomicAdd(orow + col + 1,
                          gate * (c[mf][nf][rr * 2 + 1] + b2e[col + 1]));
            }
        }
}

// ---------------- launch ------------------------------------------------------
extern "C" void kernel_launch(void* const* d_in, const int* in_sizes, int n_in,
                              void* d_out, int out_size) {
    const float* x  = (const float*)d_in[0];
    const float* Wr = (const float*)d_in[1];
    const float* br = (const float*)d_in[2];
    const float* W1 = (const float*)d_in[3];
    const float* b1 = (const float*)d_in[4];
    const float* W2 = (const float*)d_in[5];
    const float* b2 = (const float*)d_in[6];
    float* out = (float*)d_out;

    cudaFuncSetAttribute(k_mm1, cudaFuncAttributeMaxDynamicSharedMemorySize, SMEM_BYTES);
    cudaFuncSetAttribute(k_mm2, cudaFuncAttributeMaxDynamicSharedMemorySize, SMEM_BYTES);

    int n4 = out_size / 4;
    k_pre<<<(n4 + 255) / 256, 256>>>(out, n4);                          // 0
    k_conv_w<<<dim3(64, 16, 2 * EE), dim3(32, 8)>>>(W1, W2);            // 1
    k_router<<<(N_TOK * 32 + 255) / 256, 256>>>(x, Wr, br);             // 2
    k_mm1<<<dim3(HH / TN, N_TOK / TM, EE), NT, SMEM_BYTES>>>(b1);       // 3 (profiled)
    k_mm2<<<dim3(DD / TN, N_TOK / TM, EE), NT, SMEM_BYTES>>>(b2, out);  // 4
}

// round 10
// speedup vs baseline: 3.4014x; 2.0666x over previous
#include <cuda_runtime.h>
#include <cuda_bf16.h>
#include <cstdint>
#include <math.h>

#define N_TOK 4096
#define DD 1024
#define EE 8
#define HH 2048
#define CAP 4096
#define HROWS (2 * N_TOK + 128)

#define TM 128
#define TN 128
#define NT 512           // threads per GEMM CTA (16 warps, 4x4 warp grid)
#define KC 64            // bf16 k-elements per chunk = 128 bytes
#define SROW 144         // smem row stride (128B data + 16B pad)
#define AHO 0
#define ALO 18432
#define BHO 36864
#define BLO 55296
#define STAGEB 73728     // 4 matrices x 128 rows x 144 B
#define NSTAGE 3
#define SMEM_BYTES (NSTAGE * STAGEB)   // 221184

#define NCH1 (DD / KC)   // 16 chunks for GEMM1
#define NCH2 (HH / KC)   // 32 chunks for GEMM2

// ---------------- scratch ----------------------------------------------------
__device__ int   g_cnt[EE];
__device__ int   g_tok[EE * CAP];
__device__ float g_gate[EE * CAP];
__device__ __align__(256) __nv_bfloat16 g_x_hi[(size_t)N_TOK * DD];
__device__ __align__(256) __nv_bfloat16 g_x_lo[(size_t)N_TOK * DD];
__device__ __align__(256) __nv_bfloat16 g_w1_hi[(size_t)EE * HH * DD];  // [e][n=H][k=D]
__device__ __align__(256) __nv_bfloat16 g_w1_lo[(size_t)EE * HH * DD];
__device__ __align__(256) __nv_bfloat16 g_w2_hi[(size_t)EE * DD * HH];  // [e][n=D][k=H]
__device__ __align__(256) __nv_bfloat16 g_w2_lo[(size_t)EE * DD * HH];
__device__ __align__(256) __nv_bfloat16 g_h_hi[(size_t)HROWS * HH];
__device__ __align__(256) __nv_bfloat16 g_h_lo[(size_t)HROWS * HH];

// ---------------- PTX helpers -------------------------------------------------
__device__ __forceinline__ uint32_t smem_u32(const void* p) {
    uint32_t a;
    asm("{ .reg .u64 t; cvta.to.shared.u64 t, %1; cvt.u32.u64 %0, t; }"
        : "=r"(a) : "l"(p));
    return a;
}
__device__ __forceinline__ void cp16(uint32_t dst, const void* src, int sz) {
    asm volatile("cp.async.cg.shared.global [%0], [%1], 16, %2;"
                 :: "r"(dst), "l"(src), "r"(sz));
}
#define CP_COMMIT() asm volatile("cp.async.commit_group;" ::: "memory")
#define CP_WAIT2()  asm volatile("cp.async.wait_group 2;" ::: "memory")

#define LDSM4(R, a) \
    asm volatile("ldmatrix.sync.aligned.m8n8.x4.shared.b16 {%0,%1,%2,%3}, [%4];" \
                 : "=r"((R)[0]), "=r"((R)[1]), "=r"((R)[2]), "=r"((R)[3]) : "r"(a))

#define MMA(C, A, B0, B1) \
    asm volatile("mma.sync.aligned.m16n8k16.row.col.f32.bf16.bf16.f32 " \
                 "{%0,%1,%2,%3}, {%4,%5,%6,%7}, {%8,%9}, {%0,%1,%2,%3};" \
                 : "+f"((C)[0]), "+f"((C)[1]), "+f"((C)[2]), "+f"((C)[3]) \
                 : "r"((A)[0]), "r"((A)[1]), "r"((A)[2]), "r"((A)[3]), \
                   "r"(B0), "r"(B1))

// ---------------- pre: zero out + counters ------------------------------------
__global__ void k_pre(float* __restrict__ out, int n4) {
    int i = blockIdx.x * blockDim.x + threadIdx.x;
    if (i < n4) ((float4*)out)[i] = make_float4(0.f, 0.f, 0.f, 0.f);
    if (blockIdx.x == 0 && threadIdx.x < EE) g_cnt[threadIdx.x] = 0;
}

// ---------------- conv_w: transpose + split both weights ----------------------
// z<EE: W1 (K=DD,N=HH); z>=EE: W2 (K=HH,N=DD)
__global__ void k_conv_w(const float* __restrict__ W1f,
                         const float* __restrict__ W2f) {
    __shared__ float t[32][33];
    bool isW1 = blockIdx.z < EE;
    int e = isW1 ? blockIdx.z : blockIdx.z - EE;
    int K = isW1 ? DD : HH;
    int N = isW1 ? HH : DD;
    int n0 = blockIdx.x * 32;
    int k0 = blockIdx.y * 32;
    if (n0 >= N || k0 >= K) return;
    const float* We = (isW1 ? W1f : W2f) + (size_t)e * K * N;
    for (int r = threadIdx.y; r < 32; r += 8)
        t[r][threadIdx.x] = We[(size_t)(k0 + r) * N + n0 + threadIdx.x];
    __syncthreads();
    __nv_bfloat16* dhi = isW1 ? g_w1_hi : g_w2_hi;
    __nv_bfloat16* dlo = isW1 ? g_w1_lo : g_w2_lo;
    size_t base = (size_t)e * K * N;
    int tid = threadIdx.y * 32 + threadIdx.x;
    int kp  = tid & 15;          // k pair: 2*kp, 2*kp+1
    int nr0 = tid >> 4;          // 0..15
#pragma unroll
    for (int it = 0; it < 2; it++) {
        int r = nr0 + it * 16;
        float v0 = t[2 * kp][r];
        float v1 = t[2 * kp + 1][r];
        __nv_bfloat162 h2, l2;
        h2.x = __float2bfloat16(v0);
        h2.y = __float2bfloat16(v1);
        l2.x = __float2bfloat16(v0 - __bfloat162float(h2.x));
        l2.y = __float2bfloat16(v1 - __bfloat162float(h2.y));
        size_t o = base + (size_t)(n0 + r) * K + k0 + 2 * kp;
        *(__nv_bfloat162*)(dhi + o) = h2;
        *(__nv_bfloat162*)(dlo + o) = l2;
    }
}

// ---------------- router (fused x split) --------------------------------------
__global__ void k_router(const float* __restrict__ x,
                         const float* __restrict__ Wr,
                         const float* __restrict__ br) {
    int tok  = (blockIdx.x * blockDim.x + threadIdx.x) >> 5;
    int lane = threadIdx.x & 31;
    if (tok >= N_TOK) return;
    const float* xr = x + (size_t)tok * DD;
    __nv_bfloat16* xh = g_x_hi + (size_t)tok * DD;
    __nv_bfloat16* xl = g_x_lo + (size_t)tok * DD;
    float acc[EE];
#pragma unroll
    for (int e = 0; e < EE; e++) acc[e] = 0.f;
    for (int d = lane; d < DD; d += 32) {
        float xv = xr[d];
        __nv_bfloat16 hi = __float2bfloat16(xv);
        xh[d] = hi;
        xl[d] = __float2bfloat16(xv - __bfloat162float(hi));
        const float* w = Wr + d * EE;
#pragma unroll
        for (int e = 0; e < EE; e++) acc[e] += xv * w[e];
    }
#pragma unroll
    for (int e = 0; e < EE; e++) {
#pragma unroll
        for (int o = 16; o > 0; o >>= 1)
            acc[e] += __shfl_down_sync(0xffffffffu, acc[e], o);
    }
    if (lane == 0) {
        float lg[EE];
#pragma unroll
        for (int e = 0; e < EE; e++) lg[e] = acc[e] + br[e];
        int i1 = 0;
#pragma unroll
        for (int e = 1; e < EE; e++) if (lg[e] > lg[i1]) i1 = e;
        int i2 = (i1 == 0) ? 1 : 0;
#pragma unroll
        for (int e = 0; e < EE; e++)
            if (e != i1 && lg[e] > lg[i2]) i2 = e;
        float e2 = expf(lg[i2] - lg[i1]);
        float s  = 1.0f + e2;
        int s1 = atomicAdd(&g_cnt[i1], 1);
        g_tok[i1 * CAP + s1]  = tok;
        g_gate[i1 * CAP + s1] = 1.0f / s;
        int s2 = atomicAdd(&g_cnt[i2], 1);
        g_tok[i2 * CAP + s2]  = tok;
        g_gate[i2 * CAP + s2] = e2 / s;
    }
}

// ---------------- HMMA chunk: warp tile 32(m) x 32(n), split-bf16 3-product ---
__device__ __forceinline__ void hmma_chunk(uint32_t st, int mw, int nw, int lane,
                                           float c[2][4][4]) {
    uint32_t arow = lane & 15;
    uint32_t acol = (lane >> 4) * 16;
#pragma unroll
    for (int ks = 0; ks < 4; ks++) {
        uint32_t kb = ks * 32 + acol;
        uint32_t ah[2][4], al[2][4];
#pragma unroll
        for (int mf = 0; mf < 2; mf++) {
            uint32_t ro = (uint32_t)(mw * 32 + mf * 16 + arow) * SROW + kb;
            LDSM4(ah[mf], st + AHO + ro);
            LDSM4(al[mf], st + ALO + ro);
        }
#pragma unroll
        for (int p = 0; p < 2; p++) {
            uint32_t bh[4], bl[4];
            uint32_t ro = (uint32_t)(nw * 32 + p * 16 + arow) * SROW + kb;
            LDSM4(bh, st + BHO + ro);
            LDSM4(bl, st + BLO + ro);
#pragma unroll
            for (int mf = 0; mf < 2; mf++) {
                MMA(c[mf][2 * p],     ah[mf], bh[0], bh[2]);
                MMA(c[mf][2 * p + 1], ah[mf], bh[1], bh[3]);
                MMA(c[mf][2 * p],     ah[mf], bl[0], bl[2]);
                MMA(c[mf][2 * p + 1], ah[mf], bl[1], bl[3]);
                MMA(c[mf][2 * p],     al[mf], bh[0], bh[2]);
                MMA(c[mf][2 * p + 1], al[mf], bh[1], bh[3]);
            }
        }
    }
}

// issue one chunk's async loads: 512 threads x 8 cp16 = 64KB
__device__ __forceinline__ void load_bf(
    uint32_t st, const char* aH, const char* aL, const char* bH, const char* bL,
    int szA, int tid, int kbyte) {
    int row = tid >> 2;
    int j0  = (tid & 3) * 2;
#pragma unroll
    for (int j = j0; j < j0 + 2; j++) {
        uint32_t so = (uint32_t)row * SROW + j * 16;
        int go = kbyte + j * 16;
        cp16(st + AHO + so, aH + go, szA);
        cp16(st + ALO + so, aL + go, szA);
        cp16(st + BHO + so, bH + go, 16);
        cp16(st + BLO + so, bL + go, 16);
    }
}

// ---------------- GEMM1: h = relu(Xg @ W1^T + b1) -> split bf16 ---------------
__global__ void __launch_bounds__(NT) k_mm1(const float* __restrict__ b1) {
    extern __shared__ char smem[];
    int e   = blockIdx.z;
    int cnt = g_cnt[e];
    int m0  = blockIdx.y * TM;
    if (m0 >= cnt) return;
    int n0  = blockIdx.x * TN;
    int off = 0;
    for (int i = 0; i < e; i++) off += g_cnt[i];
    int tid = threadIdx.x, wid = tid >> 5, lane = tid & 31;
    int mw = wid & 3, nw = wid >> 2;
    uint32_t sbase = smem_u32(smem);

    int drow = tid >> 2;
    bool rokA = (m0 + drow) < cnt;
    int tokA = rokA ? g_tok[e * CAP + m0 + drow] : 0;
    const char* aH = (const char*)(g_x_hi + (size_t)tokA * DD);
    const char* aL = (const char*)(g_x_lo + (size_t)tokA * DD);
    const char* bH = (const char*)(g_w1_hi + ((size_t)e * HH + n0 + drow) * DD);
    const char* bL = (const char*)(g_w1_lo + ((size_t)e * HH + n0 + drow) * DD);
    int szA = rokA ? 16 : 0;

    float c[2][4][4];
#pragma unroll
    for (int i = 0; i < 2; i++)
#pragma unroll
        for (int j = 0; j < 4; j++)
#pragma unroll
            for (int q = 0; q < 4; q++) c[i][j][q] = 0.f;

    load_bf(sbase, aH, aL, bH, bL, szA, tid, 0);
    CP_COMMIT();
    load_bf(sbase + STAGEB, aH, aL, bH, bL, szA, tid, KC * 2);
    CP_COMMIT();
    for (int ch = 0; ch < NCH1; ch++) {
        if (ch + 2 < NCH1)
            load_bf(sbase + ((ch + 2) % NSTAGE) * STAGEB, aH, aL, bH, bL,
                    szA, tid, (ch + 2) * (KC * 2));
        CP_COMMIT();
        CP_WAIT2();
        __syncthreads();
        hmma_chunk(sbase + (ch % NSTAGE) * STAGEB, mw, nw, lane, c);
        __syncthreads();
    }

    // epilogue: bias + relu, split-bf16 store
    const float* b1e = b1 + (size_t)e * HH + n0;
#pragma unroll
    for (int mf = 0; mf < 2; mf++) {
#pragma unroll
        for (int rr = 0; rr < 2; rr++) {
            int row = mw * 32 + mf * 16 + (lane >> 2) + rr * 8;
            int m = m0 + row;
            if (m >= cnt) continue;
            __nv_bfloat16* phi = g_h_hi + (size_t)(off + m) * HH + n0;
            __nv_bfloat16* plo = g_h_lo + (size_t)(off + m) * HH + n0;
#pragma unroll
            for (int j = 0; j < 4; j++) {
                int col = nw * 32 + j * 8 + 2 * (lane & 3);
                float v0 = fmaxf(c[mf][j][rr * 2 + 0] + b1e[col],     0.f);
                float v1 = fmaxf(c[mf][j][rr * 2 + 1] + b1e[col + 1], 0.f);
                __nv_bfloat162 h2, l2;
                h2.x = __float2bfloat16(v0);
                h2.y = __float2bfloat16(v1);
                l2.x = __float2bfloat16(v0 - __bfloat162float(h2.x));
                l2.y = __float2bfloat16(v1 - __bfloat162float(h2.y));
                *(__nv_bfloat162*)(phi + col) = h2;
                *(__nv_bfloat162*)(plo + col) = l2;
            }
        }
    }
}

// ---------------- GEMM2: out[tok] += gate * (h @ W2^T + b2) -------------------
__global__ void __launch_bounds__(NT) k_mm2(const float* __restrict__ b2,
                                            float* __restrict__ out) {
    extern __shared__ char smem[];
    int e   = blockIdx.z;
    int cnt = g_cnt[e];
    int m0  = blockIdx.y * TM;
    if (m0 >= cnt) return;
    int n0  = blockIdx.x * TN;
    int off = 0;
    for (int i = 0; i < e; i++) off += g_cnt[i];
    int tid = threadIdx.x, wid = tid >> 5, lane = tid & 31;
    int mw = wid & 3, nw = wid >> 2;
    uint32_t sbase = smem_u32(smem);

    int drow = tid >> 2;
    bool rokA = (m0 + drow) < cnt;
    const char* aH = (const char*)(g_h_hi + (size_t)(off + m0 + drow) * HH);
    const char* aL = (const char*)(g_h_lo + (size_t)(off + m0 + drow) * HH);
    const char* bH = (const char*)(g_w2_hi + ((size_t)e * DD + n0 + drow) * HH);
    const char* bL = (const char*)(g_w2_lo + ((size_t)e * DD + n0 + drow) * HH);
    int szA = rokA ? 16 : 0;

    float c[2][4][4];
#pragma unroll
    for (int i = 0; i < 2; i++)
#pragma unroll
        for (int j = 0; j < 4; j++)
#pragma unroll
            for (int q = 0; q < 4; q++) c[i][j][q] = 0.f;

    load_bf(sbase, aH, aL, bH, bL, szA, tid, 0);
    CP_COMMIT();
    load_bf(sbase + STAGEB, aH, aL, bH, bL, szA, tid, KC * 2);
    CP_COMMIT();
    for (int ch = 0; ch < NCH2; ch++) {
        if (ch + 2 < NCH2)
            load_bf(sbase + ((ch + 2) % NSTAGE) * STAGEB, aH, aL, bH, bL,
                    szA, tid, (ch + 2) * (KC * 2));
        CP_COMMIT();
        CP_WAIT2();
        __syncthreads();
        hmma_chunk(sbase + (ch % NSTAGE) * STAGEB, mw, nw, lane, c);
        __syncthreads();
    }

    const float* b2e = b2 + (size_t)e * DD + n0;
#pragma unroll
    for (int mf = 0; mf < 2; mf++) {
#pragma unroll
        for (int rr = 0; rr < 2; rr++) {
            int row = mw * 32 + mf * 16 + (lane >> 2) + rr * 8;
            int m = m0 + row;
            if (m >= cnt) continue;
            int   tok  = g_tok[e * CAP + m];
            float gate = g_gate[e * CAP + m];
            float* orow = out + (size_t)tok * DD + n0;
#pragma unroll
            for (int j = 0; j < 4; j++) {
                int col = nw * 32 + j * 8 + 2 * (lane & 3);
                atomicAdd(orow + col,
                          gate * (c[mf][j][rr * 2 + 0] + b2e[col]));
                atomicAdd(orow + col + 1,
                          gate * (c[mf][j][rr * 2 + 1] + b2e[col + 1]));
            }
        }
    }
}

// ---------------- launch ------------------------------------------------------
extern "C" void kernel_launch(void* const* d_in, const int* in_sizes, int n_in,
                              void* d_out, int out_size) {
    const float* x  = (const float*)d_in[0];
    const float* Wr = (const float*)d_in[1];
    const float* br = (const float*)d_in[2];
    const float* W1 = (const float*)d_in[3];
    const float* b1 = (const float*)d_in[4];
    const float* W2 = (const float*)d_in[5];
    const float* b2 = (const float*)d_in[6];
    float* out = (float*)d_out;

    cudaFuncSetAttribute(k_mm1, cudaFuncAttributeMaxDynamicSharedMemorySize, SMEM_BYTES);
    cudaFuncSetAttribute(k_mm2, cudaFuncAttributeMaxDynamicSharedMemorySize, SMEM_BYTES);

    int n4 = out_size / 4;
    k_pre<<<(n4 + 255) / 256, 256>>>(out, n4);                          // 0
    k_conv_w<<<dim3(64, 64, 2 * EE), dim3(32, 8)>>>(W1, W2);            // 1
    k_router<<<(N_TOK * 32 + 255) / 256, 256>>>(x, Wr, br);             // 2
    k_mm1<<<dim3(HH / TN, N_TOK / TM, EE), NT, SMEM_BYTES>>>(b1);       // 3 (profiled)
    k_mm2<<<dim3(DD / TN, N_TOK / TM, EE), NT, SMEM_BYTES>>>(b2, out);  // 4
}

// round 11
// speedup vs baseline: 4.6059x; 1.3542x over previous
#include <cuda_runtime.h>
#include <cuda_fp16.h>
#include <cstdint>
#include <math.h>

#define N_TOK 4096
#define DD 1024
#define EE 8
#define HH 2048
#define CAP 4096
#define HROWS (2 * N_TOK + 256)

#define TM 256           // CTA rows
#define TN 128           // CTA cols
#define NT 512           // 16 warps: 4(m) x 4(n), warp tile 64x32
#define KC 64            // fp16 k-elements per chunk = 128 bytes/row
#define SROW 144         // 128B data + 16B pad
#define AO  0            // A:   256 rows x 144
#define BHO 36864        // Bhi: 128 rows x 144
#define BLO 55296        // Blo: 128 rows x 144
#define STAGEB 73728
#define NSTAGE 3
#define SMEM_BYTES (NSTAGE * STAGEB)   // 221184

#define NCH1 (DD / KC)   // 16
#define NCH2 (HH / KC)   // 32

// ---------------- scratch ----------------------------------------------------
__device__ int   g_cnt[EE];
__device__ int   g_tok[EE * CAP];
__device__ float g_gate[EE * CAP];
__device__ __align__(256) __half g_x[(size_t)N_TOK * DD];               // single fp16
__device__ __align__(256) __half g_w1_hi[(size_t)EE * HH * DD];         // [e][n=H][k=D]
__device__ __align__(256) __half g_w1_lo[(size_t)EE * HH * DD];
__device__ __align__(256) __half g_w2_hi[(size_t)EE * DD * HH];         // [e][n=D][k=H]
__device__ __align__(256) __half g_w2_lo[(size_t)EE * DD * HH];
__device__ __align__(256) __half g_h[(size_t)HROWS * HH];               // single fp16

// ---------------- PTX helpers -------------------------------------------------
__device__ __forceinline__ uint32_t smem_u32(const void* p) {
    uint32_t a;
    asm("{ .reg .u64 t; cvta.to.shared.u64 t, %1; cvt.u32.u64 %0, t; }"
        : "=r"(a) : "l"(p));
    return a;
}
__device__ __forceinline__ void cp16(uint32_t dst, const void* src, int sz) {
    asm volatile("cp.async.cg.shared.global [%0], [%1], 16, %2;"
                 :: "r"(dst), "l"(src), "r"(sz));
}
#define CP_COMMIT() asm volatile("cp.async.commit_group;" ::: "memory")
#define CP_WAIT2()  asm volatile("cp.async.wait_group 2;" ::: "memory")

#define LDSM4(R, a) \
    asm volatile("ldmatrix.sync.aligned.m8n8.x4.shared.b16 {%0,%1,%2,%3}, [%4];" \
                 : "=r"((R)[0]), "=r"((R)[1]), "=r"((R)[2]), "=r"((R)[3]) : "r"(a))

#define MMA(C, A, B0, B1) \
    asm volatile("mma.sync.aligned.m16n8k16.row.col.f32.f16.f16.f32 " \
                 "{%0,%1,%2,%3}, {%4,%5,%6,%7}, {%8,%9}, {%0,%1,%2,%3};" \
                 : "+f"((C)[0]), "+f"((C)[1]), "+f"((C)[2]), "+f"((C)[3]) \
                 : "r"((A)[0]), "r"((A)[1]), "r"((A)[2]), "r"((A)[3]), \
                   "r"(B0), "r"(B1))

// ---------------- pre: zero out + counters ------------------------------------
__global__ void k_pre(float* __restrict__ out, int n4) {
    int i = blockIdx.x * blockDim.x + threadIdx.x;
    if (i < n4) ((float4*)out)[i] = make_float4(0.f, 0.f, 0.f, 0.f);
    if (blockIdx.x == 0 && threadIdx.x < EE) g_cnt[threadIdx.x] = 0;
}

// ---------------- conv_w: transpose + fp16 split both weights -----------------
// z<EE: W1 (K=DD,N=HH); z>=EE: W2 (K=HH,N=DD)
__global__ void k_conv_w(const float* __restrict__ W1f,
                         const float* __restrict__ W2f) {
    __shared__ float t[32][33];
    bool isW1 = blockIdx.z < EE;
    int e = isW1 ? blockIdx.z : blockIdx.z - EE;
    int K = isW1 ? DD : HH;
    int N = isW1 ? HH : DD;
    int n0 = blockIdx.x * 32;
    int k0 = blockIdx.y * 32;
    if (n0 >= N || k0 >= K) return;
    const float* We = (isW1 ? W1f : W2f) + (size_t)e * K * N;
    for (int r = threadIdx.y; r < 32; r += 8)
        t[r][threadIdx.x] = We[(size_t)(k0 + r) * N + n0 + threadIdx.x];
    __syncthreads();
    __half* dhi = isW1 ? g_w1_hi : g_w2_hi;
    __half* dlo = isW1 ? g_w1_lo : g_w2_lo;
    size_t base = (size_t)e * K * N;
    int tid = threadIdx.y * 32 + threadIdx.x;
    int kp  = tid & 15;          // k pair: 2*kp, 2*kp+1
    int nr0 = tid >> 4;          // 0..15
#pragma unroll
    for (int it = 0; it < 2; it++) {
        int r = nr0 + it * 16;
        float v0 = t[2 * kp][r];
        float v1 = t[2 * kp + 1][r];
        __half h0 = __float2half(v0), h1 = __float2half(v1);
        __half l0 = __float2half(v0 - __half2float(h0));
        __half l1 = __float2half(v1 - __half2float(h1));
        size_t o = base + (size_t)(n0 + r) * K + k0 + 2 * kp;
        __half2 h2; h2.x = h0; h2.y = h1;
        __half2 l2; l2.x = l0; l2.y = l1;
        *(__half2*)(dhi + o) = h2;
        *(__half2*)(dlo + o) = l2;
    }
}

// ---------------- router (fused x -> fp16) ------------------------------------
__global__ void k_router(const float* __restrict__ x,
                         const float* __restrict__ Wr,
                         const float* __restrict__ br) {
    int tok  = (blockIdx.x * blockDim.x + threadIdx.x) >> 5;
    int lane = threadIdx.x & 31;
    if (tok >= N_TOK) return;
    const float* xr = x + (size_t)tok * DD;
    __half* xh = g_x + (size_t)tok * DD;
    float acc[EE];
#pragma unroll
    for (int e = 0; e < EE; e++) acc[e] = 0.f;
    for (int d = lane; d < DD; d += 32) {
        float xv = xr[d];
        xh[d] = __float2half(xv);
        const float* w = Wr + d * EE;
#pragma unroll
        for (int e = 0; e < EE; e++) acc[e] += xv * w[e];
    }
#pragma unroll
    for (int e = 0; e < EE; e++) {
#pragma unroll
        for (int o = 16; o > 0; o >>= 1)
            acc[e] += __shfl_down_sync(0xffffffffu, acc[e], o);
    }
    if (lane == 0) {
        float lg[EE];
#pragma unroll
        for (int e = 0; e < EE; e++) lg[e] = acc[e] + br[e];
        int i1 = 0;
#pragma unroll
        for (int e = 1; e < EE; e++) if (lg[e] > lg[i1]) i1 = e;
        int i2 = (i1 == 0) ? 1 : 0;
#pragma unroll
        for (int e = 0; e < EE; e++)
            if (e != i1 && lg[e] > lg[i2]) i2 = e;
        float e2 = expf(lg[i2] - lg[i1]);
        float s  = 1.0f + e2;
        int s1 = atomicAdd(&g_cnt[i1], 1);
        g_tok[i1 * CAP + s1]  = tok;
        g_gate[i1 * CAP + s1] = 1.0f / s;
        int s2 = atomicAdd(&g_cnt[i2], 1);
        g_tok[i2 * CAP + s2]  = tok;
        g_gate[i2 * CAP + s2] = e2 / s;
    }
}

// ---------------- HMMA chunk: warp tile 64(m) x 32(n), 2-product fp16 ---------
__device__ __forceinline__ void hmma_chunk(uint32_t st, int mw, int nw, int lane,
                                           float c[4][4][4]) {
    uint32_t arow = lane & 15;
    uint32_t acol = (lane >> 4) * 16;
#pragma unroll
    for (int ks = 0; ks < 4; ks++) {
        uint32_t kb = ks * 32 + acol;
        uint32_t a[4][4];
#pragma unroll
        for (int mf = 0; mf < 4; mf++)
            LDSM4(a[mf], st + AO + (uint32_t)(mw * 64 + mf * 16 + arow) * SROW + kb);
#pragma unroll
        for (int p = 0; p < 2; p++) {
            uint32_t bh[4], bl[4];
            uint32_t ro = (uint32_t)(nw * 32 + p * 16 + arow) * SROW + kb;
            LDSM4(bh, st + BHO + ro);
            LDSM4(bl, st + BLO + ro);
#pragma unroll
            for (int mf = 0; mf < 4; mf++) {
                MMA(c[mf][2 * p],     a[mf], bh[0], bh[2]);
                MMA(c[mf][2 * p + 1], a[mf], bh[1], bh[3]);
                MMA(c[mf][2 * p],     a[mf], bl[0], bl[2]);
                MMA(c[mf][2 * p + 1], a[mf], bl[1], bl[3]);
            }
        }
    }
}

// issue one chunk's async loads: 512 threads x 8 cp16 = 72KB (incl pads)
__device__ __forceinline__ void load_fp16(
    uint32_t st, const char* aP, const char* bH, const char* bL,
    int szA, int tid, int kbyte) {
    int rowA = tid >> 1;             // 0..255
    int jA   = (tid & 1) * 4;
#pragma unroll
    for (int j = 0; j < 4; j++) {
        cp16(st + AO + (uint32_t)rowA * SROW + (jA + j) * 16,
             aP + kbyte + (jA + j) * 16, szA);
    }
    int rowB = tid >> 2;             // 0..127
    int jB   = (tid & 3) * 2;
#pragma unroll
    for (int j = 0; j < 2; j++) {
        uint32_t so = (uint32_t)rowB * SROW + (jB + j) * 16;
        int go = kbyte + (jB + j) * 16;
        cp16(st + BHO + so, bH + go, 16);
        cp16(st + BLO + so, bL + go, 16);
    }
}

// ---------------- GEMM1: h = relu(Xg @ W1^T + b1) -> fp16 ---------------------
__global__ void __launch_bounds__(NT) k_mm1(const float* __restrict__ b1) {
    extern __shared__ char smem[];
    int e   = blockIdx.z;
    int cnt = g_cnt[e];
    int m0  = blockIdx.y * TM;
    if (m0 >= cnt) return;
    int n0  = blockIdx.x * TN;
    int off = 0;
    for (int i = 0; i < e; i++) off += g_cnt[i];
    int tid = threadIdx.x, wid = tid >> 5, lane = tid & 31;
    int mw = wid & 3, nw = wid >> 2;
    uint32_t sbase = smem_u32(smem);

    int drow = tid >> 1;
    bool rokA = (m0 + drow) < cnt;
    int tokA = rokA ? g_tok[e * CAP + m0 + drow] : 0;
    const char* aP = (const char*)(g_x + (size_t)tokA * DD);
    const char* bH = (const char*)(g_w1_hi + ((size_t)e * HH + n0 + (tid >> 2)) * DD);
    const char* bL = (const char*)(g_w1_lo + ((size_t)e * HH + n0 + (tid >> 2)) * DD);
    int szA = rokA ? 16 : 0;

    float c[4][4][4];
#pragma unroll
    for (int i = 0; i < 4; i++)
#pragma unroll
        for (int j = 0; j < 4; j++)
#pragma unroll
            for (int q = 0; q < 4; q++) c[i][j][q] = 0.f;

    load_fp16(sbase, aP, bH, bL, szA, tid, 0);
    CP_COMMIT();
    load_fp16(sbase + STAGEB, aP, bH, bL, szA, tid, KC * 2);
    CP_COMMIT();
    for (int ch = 0; ch < NCH1; ch++) {
        if (ch + 2 < NCH1)
            load_fp16(sbase + ((ch + 2) % NSTAGE) * STAGEB, aP, bH, bL,
                      szA, tid, (ch + 2) * (KC * 2));
        CP_COMMIT();
        CP_WAIT2();
        __syncthreads();
        hmma_chunk(sbase + (ch % NSTAGE) * STAGEB, mw, nw, lane, c);
        __syncthreads();
    }

    // epilogue: bias + relu, single-fp16 store
    const float* b1e = b1 + (size_t)e * HH + n0;
#pragma unroll
    for (int mf = 0; mf < 4; mf++) {
#pragma unroll
        for (int rr = 0; rr < 2; rr++) {
            int row = mw * 64 + mf * 16 + (lane >> 2) + rr * 8;
            int m = m0 + row;
            if (m >= cnt) continue;
            __half* ph = g_h + (size_t)(off + m) * HH + n0;
#pragma unroll
            for (int j = 0; j < 4; j++) {
                int col = nw * 32 + j * 8 + 2 * (lane & 3);
                float v0 = fmaxf(c[mf][j][rr * 2 + 0] + b1e[col],     0.f);
                float v1 = fmaxf(c[mf][j][rr * 2 + 1] + b1e[col + 1], 0.f);
                __half2 hv; hv.x = __float2half(v0); hv.y = __float2half(v1);
                *(__half2*)(ph + col) = hv;
            }
        }
    }
}

// ---------------- GEMM2: out[tok] += gate * (h @ W2^T + b2) -------------------
__global__ void __launch_bounds__(NT) k_mm2(const float* __restrict__ b2,
                                            float* __restrict__ out) {
    extern __shared__ char smem[];
    int e   = blockIdx.z;
    int cnt = g_cnt[e];
    int m0  = blockIdx.y * TM;
    if (m0 >= cnt) return;
    int n0  = blockIdx.x * TN;
    int off = 0;
    for (int i = 0; i < e; i++) off += g_cnt[i];
    int tid = threadIdx.x, wid = tid >> 5, lane = tid & 31;
    int mw = wid & 3, nw = wid >> 2;
    uint32_t sbase = smem_u32(smem);

    int drow = tid >> 1;
    bool rokA = (m0 + drow) < cnt;
    const char* aP = (const char*)(g_h + (size_t)(off + m0 + drow) * HH);
    const char* bH = (const char*)(g_w2_hi + ((size_t)e * DD + n0 + (tid >> 2)) * HH);
    const char* bL = (const char*)(g_w2_lo + ((size_t)e * DD + n0 + (tid >> 2)) * HH);
    int szA = rokA ? 16 : 0;

    float c[4][4][4];
#pragma unroll
    for (int i = 0; i < 4; i++)
#pragma unroll
        for (int j = 0; j < 4; j++)
#pragma unroll
            for (int q = 0; q < 4; q++) c[i][j][q] = 0.f;

    load_fp16(sbase, aP, bH, bL, szA, tid, 0);
    CP_COMMIT();
    load_fp16(sbase + STAGEB, aP, bH, bL, szA, tid, KC * 2);
    CP_COMMIT();
    for (int ch = 0; ch < NCH2; ch++) {
        if (ch + 2 < NCH2)
            load_fp16(sbase + ((ch + 2) % NSTAGE) * STAGEB, aP, bH, bL,
                      szA, tid, (ch + 2) * (KC * 2));
        CP_COMMIT();
        CP_WAIT2();
        __syncthreads();
        hmma_chunk(sbase + (ch % NSTAGE) * STAGEB, mw, nw, lane, c);
        __syncthreads();
    }

    const float* b2e = b2 + (size_t)e * DD + n0;
#pragma unroll
    for (int mf = 0; mf < 4; mf++) {
#pragma unroll
        for (int rr = 0; rr < 2; rr++) {
            int row = mw * 64 + mf * 16 + (lane >> 2) + rr * 8;
            int m = m0 + row;
            if (m >= cnt) continue;
            int   tok  = g_tok[e * CAP + m];
            float gate = g_gate[e * CAP + m];
            float* orow = out + (size_t)tok * DD + n0;
#pragma unroll
            for (int j = 0; j < 4; j++) {
                int col = nw * 32 + j * 8 + 2 * (lane & 3);
                atomicAdd(orow + col,
                          gate * (c[mf][j][rr * 2 + 0] + b2e[col]));
                atomicAdd(orow + col + 1,
                          gate * (c[mf][j][rr * 2 + 1] + b2e[col + 1]));
            }
        }
    }
}

// ---------------- launch ------------------------------------------------------
extern "C" void kernel_launch(void* const* d_in, const int* in_sizes, int n_in,
                              void* d_out, int out_size) {
    const float* x  = (const float*)d_in[0];
    const float* Wr = (const float*)d_in[1];
    const float* br = (const float*)d_in[2];
    const float* W1 = (const float*)d_in[3];
    const float* b1 = (const float*)d_in[4];
    const float* W2 = (const float*)d_in[5];
    const float* b2 = (const float*)d_in[6];
    float* out = (float*)d_out;

    cudaFuncSetAttribute(k_mm1, cudaFuncAttributeMaxDynamicSharedMemorySize, SMEM_BYTES);
    cudaFuncSetAttribute(k_mm2, cudaFuncAttributeMaxDynamicSharedMemorySize, SMEM_BYTES);

    int n4 = out_size / 4;
    k_pre<<<(n4 + 255) / 256, 256>>>(out, n4);                            // 0
    k_conv_w<<<dim3(64, 64, 2 * EE), dim3(32, 8)>>>(W1, W2);              // 1
    k_router<<<(N_TOK * 32 + 255) / 256, 256>>>(x, Wr, br);               // 2
    k_mm1<<<dim3(HH / TN, CAP / TM, EE), NT, SMEM_BYTES>>>(b1);           // 3 (profiled)
    k_mm2<<<dim3(DD / TN, CAP / TM, EE), NT, SMEM_BYTES>>>(b2, out);      // 4
}